// round 10
// baseline (speedup 1.0000x reference)
#include <cuda_runtime.h>
#include <cstdint>

// axon_layer: dual-exponential PSP scan.
//   m_t = m_{t-1}*dm + x_t ; s_t = s_{t-1}*ds + x_t ; psp_t = (m_t - s_t)*v0
//
// Bulk-async design: ALL gmem<->smem traffic goes through cp.async.bulk (TMA
// engine), not warp LSU instructions. Each thread owns one row; each bulk op
// moves that thread's contiguous 400B row-chunk. Load stages complete via
// mbarrier (expect_tx 400/thread); store stages drain via per-thread
// bulk_group (wait_group.read gates reuse). Staging is thread-private ->
// no __syncthreads in the main loop. Warp LSU only does the conflict-free
// LDS/STS of the scan itself (~4x less LSU work per byte than R9).
//
// Inputs: [0] input_spikes f32 [B,F,T]  [1] decay_m f32 [F]
//         [2] decay_s f32 [F]           [3] v_0 f32 scalar
// Output: psps [B,F,T] then m_T [B,F] then s_T [B,F].

#define AXT        400
#define AX_CHF     100                 // floats per chunk per row
#define AX_CHB     400                 // bytes per chunk per row
#define AX_NCH     4
#define AX_ROWS    64
#define AX_THREADS 64
#define AX_STAGEB  (AX_ROWS * AX_CHB)  // 25600 B per stage

// smem byte offsets
#define SM_MBAR0   0
#define SM_MBAR1   8
#define SM_LOAD0   128
#define SM_LOAD1   (SM_LOAD0  + AX_STAGEB)
#define SM_STORE0  (SM_LOAD1  + AX_STAGEB)
#define SM_STORE1  (SM_STORE0 + AX_STAGEB)
#define SM_TOTAL   (SM_STORE1 + AX_STAGEB)   // 102528 B -> 2 blocks/SM

__device__ __forceinline__ uint32_t ax_s32(const void* p) {
    return (uint32_t)__cvta_generic_to_shared(p);
}
__device__ __forceinline__ void ax_mbar_init(uint32_t mbar, uint32_t cnt) {
    asm volatile("mbarrier.init.shared.b64 [%0], %1;" :: "r"(mbar), "r"(cnt) : "memory");
}
__device__ __forceinline__ void ax_expect_tx(uint32_t mbar, uint32_t bytes) {
    asm volatile("mbarrier.arrive.expect_tx.shared.b64 _, [%0], %1;"
                 :: "r"(mbar), "r"(bytes) : "memory");
}
__device__ __forceinline__ void ax_wait_parity(uint32_t mbar, uint32_t parity) {
    uint32_t done;
    asm volatile(
        "{\n\t.reg .pred p;\n\t"
        "mbarrier.try_wait.parity.acquire.cta.shared::cta.b64 p, [%1], %2;\n\t"
        "selp.b32 %0, 1, 0, p;\n\t}"
        : "=r"(done) : "r"(mbar), "r"(parity) : "memory");
    if (!done) {
        asm volatile(
            "{\n\t.reg .pred P1;\n\t"
            "WL_%=:\n\t"
            "mbarrier.try_wait.parity.acquire.cta.shared::cta.b64 P1, [%0], %1, 0x989680;\n\t"
            "@P1 bra.uni WD_%=;\n\t"
            "bra.uni WL_%=;\n\t"
            "WD_%=:\n\t}"
            :: "r"(mbar), "r"(parity) : "memory");
    }
}
__device__ __forceinline__ void ax_bulk_g2s(uint32_t sdst, const void* gsrc,
                                            uint32_t bytes, uint32_t mbar) {
    asm volatile(
        "cp.async.bulk.shared::cta.global.mbarrier::complete_tx::bytes "
        "[%0], [%1], %2, [%3];"
        :: "r"(sdst), "l"(gsrc), "r"(bytes), "r"(mbar) : "memory");
}
__device__ __forceinline__ void ax_bulk_s2g(void* gdst, uint32_t ssrc, uint32_t bytes) {
    asm volatile(
        "cp.async.bulk.global.shared::cta.bulk_group [%0], [%1], %2;"
        :: "l"(gdst), "r"(ssrc), "r"(bytes) : "memory");
}
__device__ __forceinline__ void ax_bulk_commit() {
    asm volatile("cp.async.bulk.commit_group;" ::: "memory");
}
__device__ __forceinline__ void ax_bulk_wait_read1() {
    asm volatile("cp.async.bulk.wait_group.read 1;" ::: "memory");
}
__device__ __forceinline__ void ax_bulk_wait_all() {
    asm volatile("cp.async.bulk.wait_group 0;" ::: "memory");
}

extern __shared__ char ax_smem[];

__global__ void __launch_bounds__(AX_THREADS)
axon_bulk_kernel(const float* __restrict__ x,
                 const float* __restrict__ decay_m,
                 const float* __restrict__ decay_s,
                 const float* __restrict__ v0p,
                 float* __restrict__ out,
                 int F, long long n_rows)
{
    const int tid = threadIdx.x;
    const long long row = (long long)blockIdx.x * AX_ROWS + tid;

    const float dm = __ldg(&decay_m[(int)(row % F)]);
    const float ds = __ldg(&decay_s[(int)(row % F)]);
    const float v0 = __ldg(v0p);

    const char* gsrc = (const char*)(x + row * AXT);   // this thread's row
    char*       gdst = (char*)(out + row * AXT);

    const uint32_t sbase = ax_s32(ax_smem);
    const uint32_t mbar[2] = { sbase + SM_MBAR0, sbase + SM_MBAR1 };
    const uint32_t ld[2]   = { sbase + SM_LOAD0  + (uint32_t)tid * AX_CHB,
                               sbase + SM_LOAD1  + (uint32_t)tid * AX_CHB };
    const uint32_t st[2]   = { sbase + SM_STORE0 + (uint32_t)tid * AX_CHB,
                               sbase + SM_STORE1 + (uint32_t)tid * AX_CHB };

    if (tid == 0) {
        ax_mbar_init(mbar[0], AX_THREADS);
        ax_mbar_init(mbar[1], AX_THREADS);
    }
    __syncthreads();   // mbarriers visible before any bulk targets them

    // ---- prologue: chunks 0 and 1 in flight (each thread loads its row slice) ----
    ax_expect_tx(mbar[0], AX_CHB);
    ax_bulk_g2s(ld[0], gsrc,           AX_CHB, mbar[0]);
    ax_expect_tx(mbar[1], AX_CHB);
    ax_bulk_g2s(ld[1], gsrc + AX_CHB,  AX_CHB, mbar[1]);

    float m = 0.0f, s = 0.0f;

#pragma unroll
    for (int ch = 0; ch < AX_NCH; ++ch) {
        const int b = ch & 1;

        ax_wait_parity(mbar[b], (ch >> 1) & 1);   // load chunk ch resident
        ax_bulk_wait_read1();                     // store-stage b free (per-thread)

        const float4* lb = (const float4*)(ax_smem + (b ? SM_LOAD1  : SM_LOAD0)
                                           + tid * AX_CHB);
        float4*       sb = (float4*)(ax_smem + (b ? SM_STORE1 : SM_STORE0)
                                     + tid * AX_CHB);

        // ---- sequential scan of this thread's 100 elements (bit-exact) ----
#pragma unroll
        for (int q = 0; q < AX_CHF / 4; ++q) {    // 25 quads, stride-25: conflict-free
            float4 v = lb[q];
            float4 o;
            m = fmaf(m, dm, v.x); s = fmaf(s, ds, v.x); o.x = (m - s) * v0;
            m = fmaf(m, dm, v.y); s = fmaf(s, ds, v.y); o.y = (m - s) * v0;
            m = fmaf(m, dm, v.z); s = fmaf(s, ds, v.z); o.z = (m - s) * v0;
            m = fmaf(m, dm, v.w); s = fmaf(s, ds, v.w); o.w = (m - s) * v0;
            sb[q] = o;
        }

        // make STS visible to the async proxy, then stream out via bulk store
        asm volatile("fence.proxy.async.shared::cta;" ::: "memory");
        ax_bulk_s2g(gdst + ch * AX_CHB, st[b], AX_CHB);
        ax_bulk_commit();

        // refill this load stage with chunk ch+2 (thread-private slice)
        if (ch + 2 < AX_NCH) {
            ax_expect_tx(mbar[b], AX_CHB);
            ax_bulk_g2s(ld[b], gsrc + (ch + 2) * AX_CHB, AX_CHB, mbar[b]);
        }
    }

    // ---- final states ----
    const long long psps = n_rows * AXT;
    out[psps + row]          = m;
    out[psps + n_rows + row] = s;

    ax_bulk_wait_all();   // ensure bulk stores complete before exit
}

extern "C" void kernel_launch(void* const* d_in, const int* in_sizes, int n_in,
                              void* d_out, int out_size)
{
    const float* x   = (const float*)d_in[0];
    const float* dmv = (const float*)d_in[1];
    const float* dsv = (const float*)d_in[2];
    const float* v0p = (const float*)d_in[3];
    float* out = (float*)d_out;

    const int F = in_sizes[1];                       // 4096
    const long long total = (long long)in_sizes[0];  // B*F*T
    const long long n_rows = total / AXT;            // 131072
    const int grid = (int)(n_rows / AX_ROWS);        // 2048

    static bool attr_set = false;
    if (!attr_set) {
        cudaFuncSetAttribute(axon_bulk_kernel,
                             cudaFuncAttributeMaxDynamicSharedMemorySize,
                             SM_TOTAL);
        attr_set = true;
    }

    axon_bulk_kernel<<<grid, AX_THREADS, SM_TOTAL>>>(
        x, dmv, dsv, v0p, out, F, n_rows);
}